// round 1
// baseline (speedup 1.0000x reference)
#include <cuda_runtime.h>

#define BM 64
#define BN 64
#define DH 64
#define SSTRIDE 68          // padded smem row stride (floats); 4*tc mod 32 -> conflict-free
#define HEADS 16
#define HIDDEN 1024
#define QSCALE 0.03125f     // 1/sqrt(1024)
#define NEGBIG (-1e9f)
#define SEQ 2048

// Flash-attention (causal, K/V swapped per reference):
//   scores = Q @ Z^T * scale + NEG*mask ; out = softmax(scores) @ Y
__global__ __launch_bounds__(256)
void fa_fp32_kernel(const float* __restrict__ X,   // Q source
                    const float* __restrict__ Y,   // V_eff source
                    const float* __restrict__ Z,   // K_eff source
                    const float* __restrict__ PAD,
                    float* __restrict__ OUT,
                    int S)
{
    extern __shared__ float smem[];
    float* Qs = smem;                       // [64][68]
    float* Ks = smem + BM * SSTRIDE;        // [64][68], reused as P after scores
    float* Vs = smem + 2 * BM * SSTRIDE;    // [64][68]
    float* Ps = Ks;

    const int qt  = blockIdx.x;
    const int h   = blockIdx.y;
    const int b   = blockIdx.z;
    const int tid = threadIdx.x;
    const int tr  = tid >> 4;    // 0..15  -> rows {tr, tr+16, tr+32, tr+48}
    const int tc  = tid & 15;    // 0..15  -> cols {tc, tc+16, tc+32, tc+48}

    const int q0 = qt * BM;

    const float* Qg   = X + (size_t)b * S * HIDDEN + h * DH;
    const float* Kg   = Z + (size_t)b * S * HIDDEN + h * DH;   // K_eff = z
    const float* Vg   = Y + (size_t)b * S * HIDDEN + h * DH;   // V_eff = y
    const float* padg = PAD + (size_t)b * S;

    // ---- load Q tile (64 rows x 64 floats) into padded smem ----
    #pragma unroll
    for (int r = 0; r < 4; r++) {
        int idx = tid + 256 * r;          // 0..1023 -> 64 rows x 16 float4
        int row = idx >> 4;
        int c4  = idx & 15;
        float4 v = *(const float4*)(Qg + (size_t)(q0 + row) * HIDDEN + c4 * 4);
        *(float4*)(Qs + row * SSTRIDE + c4 * 4) = v;
    }

    float O[4][4];
    float m_i[4], l_i[4];
    #pragma unroll
    for (int i = 0; i < 4; i++) {
        m_i[i] = -1e30f; l_i[i] = 0.f;
        #pragma unroll
        for (int j = 0; j < 4; j++) O[i][j] = 0.f;
    }

    const int ktiles = qt + 1;   // causal
    for (int kt = 0; kt < ktiles; kt++) {
        __syncthreads();   // previous iteration's smem readers done
        const int k0 = kt * BN;

        // ---- load K_eff / V_eff tiles ----
        #pragma unroll
        for (int r = 0; r < 4; r++) {
            int idx = tid + 256 * r;
            int row = idx >> 4;
            int c4  = idx & 15;
            *(float4*)(Ks + row * SSTRIDE + c4 * 4) =
                *(const float4*)(Kg + (size_t)(k0 + row) * HIDDEN + c4 * 4);
            *(float4*)(Vs + row * SSTRIDE + c4 * 4) =
                *(const float4*)(Vg + (size_t)(k0 + row) * HIDDEN + c4 * 4);
        }
        __syncthreads();

        // ---- score GEMM: Sc[i][j] = Q[row_i] . K[key_j] ----
        float Sc[4][4];
        #pragma unroll
        for (int i = 0; i < 4; i++)
            #pragma unroll
            for (int j = 0; j < 4; j++) Sc[i][j] = 0.f;

        #pragma unroll
        for (int d4 = 0; d4 < 16; d4++) {
            float4 a[4], bb[4];
            #pragma unroll
            for (int i = 0; i < 4; i++)
                a[i] = *(float4*)(Qs + (tr + 16 * i) * SSTRIDE + d4 * 4);
            #pragma unroll
            for (int j = 0; j < 4; j++)
                bb[j] = *(float4*)(Ks + (tc + 16 * j) * SSTRIDE + d4 * 4);
            #pragma unroll
            for (int i = 0; i < 4; i++)
                #pragma unroll
                for (int j = 0; j < 4; j++) {
                    Sc[i][j] += a[i].x * bb[j].x;
                    Sc[i][j] += a[i].y * bb[j].y;
                    Sc[i][j] += a[i].z * bb[j].z;
                    Sc[i][j] += a[i].w * bb[j].w;
                }
        }
        __syncthreads();   // done reading Ks before overwriting with P

        // ---- scale + mask (exactly: s*scale + NEG*max(causal, 1-pad)) ----
        float pad4[4];
        #pragma unroll
        for (int j = 0; j < 4; j++) pad4[j] = padg[k0 + tc + 16 * j];

        #pragma unroll
        for (int i = 0; i < 4; i++) {
            int q = q0 + tr + 16 * i;
            #pragma unroll
            for (int j = 0; j < 4; j++) {
                int k = k0 + tc + 16 * j;
                float maskv = fmaxf((k > q) ? 1.f : 0.f, 1.f - pad4[j]);
                Sc[i][j] = Sc[i][j] * QSCALE + NEGBIG * maskv;
            }
        }

        // ---- online softmax (row groups = 16 consecutive lanes) ----
        #pragma unroll
        for (int i = 0; i < 4; i++) {
            float mx = fmaxf(fmaxf(Sc[i][0], Sc[i][1]), fmaxf(Sc[i][2], Sc[i][3]));
            #pragma unroll
            for (int off = 1; off < 16; off <<= 1)
                mx = fmaxf(mx, __shfl_xor_sync(0xffffffffu, mx, off));
            float mnew  = fmaxf(m_i[i], mx);
            float alpha = __expf(m_i[i] - mnew);
            m_i[i] = mnew;
            float rs = 0.f;
            #pragma unroll
            for (int j = 0; j < 4; j++) {
                float p = __expf(Sc[i][j] - mnew);
                Sc[i][j] = p;
                rs += p;
            }
            #pragma unroll
            for (int off = 1; off < 16; off <<= 1)
                rs += __shfl_xor_sync(0xffffffffu, rs, off);
            l_i[i] = l_i[i] * alpha + rs;
            #pragma unroll
            for (int j = 0; j < 4; j++) O[i][j] *= alpha;
        }

        // ---- write P tile into smem (overlaying Ks) ----
        #pragma unroll
        for (int i = 0; i < 4; i++)
            #pragma unroll
            for (int j = 0; j < 4; j++)
                Ps[(tr + 16 * i) * SSTRIDE + tc + 16 * j] = Sc[i][j];
        __syncthreads();

        // ---- PV GEMM: O[i][j] += sum_k P[row_i][k] * V[k][dim_j] ----
        #pragma unroll
        for (int k4 = 0; k4 < 16; k4++) {
            float4 pa[4];
            #pragma unroll
            for (int i = 0; i < 4; i++)
                pa[i] = *(float4*)(Ps + (tr + 16 * i) * SSTRIDE + k4 * 4);
            #pragma unroll
            for (int kk = 0; kk < 4; kk++) {
                const int key = k4 * 4 + kk;
                float vb[4];
                #pragma unroll
                for (int j = 0; j < 4; j++)
                    vb[j] = Vs[key * SSTRIDE + tc + 16 * j];
                #pragma unroll
                for (int i = 0; i < 4; i++) {
                    float pv = (kk == 0) ? pa[i].x : (kk == 1) ? pa[i].y
                             : (kk == 2) ? pa[i].z : pa[i].w;
                    #pragma unroll
                    for (int j = 0; j < 4; j++) O[i][j] += pv * vb[j];
                }
            }
        }
    }

    // ---- epilogue: normalize and store ----
    float* Og = OUT + (size_t)b * S * HIDDEN + h * DH;
    #pragma unroll
    for (int i = 0; i < 4; i++) {
        float inv = 1.f / l_i[i];
        int q = q0 + tr + 16 * i;
        #pragma unroll
        for (int j = 0; j < 4; j++)
            Og[(size_t)q * HIDDEN + tc + 16 * j] = O[i][j] * inv;
    }
}

extern "C" void kernel_launch(void* const* d_in, const int* in_sizes, int n_in,
                              void* d_out, int out_size)
{
    const float* x   = (const float*)d_in[0];
    const float* y   = (const float*)d_in[1];
    const float* z   = (const float*)d_in[2];
    const float* pad = (const float*)d_in[3];
    float* out = (float*)d_out;

    const int S = SEQ;
    const int B = in_sizes[3] / S;   // pad_mask is [B, S]

    const size_t smem_bytes = 3 * BM * SSTRIDE * sizeof(float);  // 52224 B
    cudaFuncSetAttribute(fa_fp32_kernel,
                         cudaFuncAttributeMaxDynamicSharedMemorySize,
                         (int)smem_bytes);

    dim3 grid(S / BM, HEADS, B);
    fa_fp32_kernel<<<grid, 256, smem_bytes>>>(x, y, z, pad, out, S);
}

// round 2
// speedup vs baseline: 2.4258x; 2.4258x over previous
#include <cuda_runtime.h>
#include <cstdint>

#define HEADS 16
#define HIDDEN 1024
#define DH 64
#define SK 68                 // smem row stride (words): 4g+l4 patterns conflict-free
#define QSCALE 0.03125f       // 1/sqrt(1024)
#define NEGBIG (-1e9f)
#define SEQ 2048

__device__ __forceinline__ uint32_t f2tf(float f) {
    uint32_t r; asm("cvt.rna.tf32.f32 %0, %1;" : "=r"(r) : "f"(f)); return r;
}

__device__ __forceinline__ void mma8(float* c,
                                     uint32_t a0, uint32_t a1, uint32_t a2, uint32_t a3,
                                     uint32_t b0, uint32_t b1) {
    asm volatile("mma.sync.aligned.m16n8k8.row.col.f32.tf32.tf32.f32 "
                 "{%0,%1,%2,%3},{%4,%5,%6,%7},{%8,%9},{%0,%1,%2,%3};"
                 : "+f"(c[0]), "+f"(c[1]), "+f"(c[2]), "+f"(c[3])
                 : "r"(a0), "r"(a1), "r"(a2), "r"(a3), "r"(b0), "r"(b1));
}

// Flash attention, causal, K/V swapped per reference:
//   scores = Q @ Z^T * scale + NEG*max(causal, 1-pad); out = softmax(scores) @ Y
__global__ __launch_bounds__(128)
void fa_tf32_kernel(const float* __restrict__ X,   // Q source
                    const float* __restrict__ Y,   // V_eff source
                    const float* __restrict__ Z,   // K_eff source
                    const float* __restrict__ PAD,
                    float* __restrict__ OUT,
                    int S)
{
    extern __shared__ uint32_t sm[];
    uint32_t* Qs = sm;               // [64][SK] tf32
    uint32_t* Ks = Qs + 64 * SK;     // [64][SK] tf32
    uint32_t* Vs = Ks + 64 * SK;     // [64][SK] tf32
    uint32_t* Ps = Vs + 64 * SK;     // [64][SK] tf32 (warp-private rows)
    float*  padS = (float*)(Ps + 64 * SK);  // [64]

    const int qt  = blockIdx.x;
    const int h   = blockIdx.y;
    const int b   = blockIdx.z;
    const int tid = threadIdx.x;
    const int w    = tid >> 5;
    const int lane = tid & 31;
    const int g    = lane >> 2;   // 0..7
    const int l4   = lane & 3;    // 0..3
    const int rb   = w * 16;      // warp's q-row block within the 64-row tile
    const int q0   = qt * 64;

    const float* Qg   = X + (size_t)b * S * HIDDEN + h * DH;
    const float* Kg   = Z + (size_t)b * S * HIDDEN + h * DH;   // K_eff = z
    const float* Vg   = Y + (size_t)b * S * HIDDEN + h * DH;   // V_eff = y
    const float* padg = PAD + (size_t)b * S;

    // ---- load + convert Q tile (64 x 64) ----
    #pragma unroll
    for (int r = 0; r < 8; r++) {
        int idx = tid + 128 * r;              // 0..1023: 64 rows x 16 float4
        int row = idx >> 4, c4 = idx & 15;
        float4 v = *(const float4*)(Qg + (size_t)(q0 + row) * HIDDEN + c4 * 4);
        uint32_t* d = Qs + row * SK + c4 * 4;
        d[0] = f2tf(v.x); d[1] = f2tf(v.y); d[2] = f2tf(v.z); d[3] = f2tf(v.w);
    }

    float O[8][4];
    #pragma unroll
    for (int nt = 0; nt < 8; nt++)
        #pragma unroll
        for (int i = 0; i < 4; i++) O[nt][i] = 0.f;
    float mrow[2] = {-1e30f, -1e30f};
    float lrow[2] = {0.f, 0.f};

    for (int kt = 0; kt <= qt; kt++) {
        __syncthreads();                       // prior iter's Ks/Vs readers done
        const int k0 = kt * 64;

        // ---- load + convert K_eff / V_eff tiles, stage pad row ----
        #pragma unroll
        for (int r = 0; r < 8; r++) {
            int idx = tid + 128 * r;
            int row = idx >> 4, c4 = idx & 15;
            float4 kv = *(const float4*)(Kg + (size_t)(k0 + row) * HIDDEN + c4 * 4);
            float4 vv = *(const float4*)(Vg + (size_t)(k0 + row) * HIDDEN + c4 * 4);
            uint32_t* dk = Ks + row * SK + c4 * 4;
            dk[0] = f2tf(kv.x); dk[1] = f2tf(kv.y); dk[2] = f2tf(kv.z); dk[3] = f2tf(kv.w);
            uint32_t* dv = Vs + row * SK + c4 * 4;
            dv[0] = f2tf(vv.x); dv[1] = f2tf(vv.y); dv[2] = f2tf(vv.z); dv[3] = f2tf(vv.w);
        }
        if (tid < 16)
            *(float4*)(padS + tid * 4) = *(const float4*)(padg + k0 + tid * 4);
        __syncthreads();

        // ---- score GEMM: c = Q(16x64) @ K^T -> 16x64 per warp ----
        float c[8][4];
        #pragma unroll
        for (int nt = 0; nt < 8; nt++)
            #pragma unroll
            for (int i = 0; i < 4; i++) c[nt][i] = 0.f;

        #pragma unroll
        for (int k8 = 0; k8 < 8; k8++) {
            const uint32_t* qr = Qs + (rb + g) * SK + k8 * 8 + l4;
            uint32_t a0 = qr[0];
            uint32_t a1 = qr[8 * SK];
            uint32_t a2 = qr[4];
            uint32_t a3 = qr[8 * SK + 4];
            #pragma unroll
            for (int nt = 0; nt < 8; nt++) {
                const uint32_t* kr = Ks + (nt * 8 + g) * SK + k8 * 8 + l4;
                mma8(c[nt], a0, a1, a2, a3, kr[0], kr[4]);
            }
        }

        // ---- scale + mask + online softmax (rows = quad groups) ----
        #pragma unroll
        for (int half = 0; half < 2; half++) {
            const int q = q0 + rb + g + 8 * half;
            float mx = -1e30f;
            #pragma unroll
            for (int nt = 0; nt < 8; nt++) {
                #pragma unroll
                for (int d = 0; d < 2; d++) {
                    int kcl = nt * 8 + 2 * l4 + d;
                    int k = k0 + kcl;
                    float maskv = fmaxf((k > q) ? 1.f : 0.f, 1.f - padS[kcl]);
                    float val = c[nt][2 * half + d] * QSCALE + NEGBIG * maskv;
                    c[nt][2 * half + d] = val;
                    mx = fmaxf(mx, val);
                }
            }
            mx = fmaxf(mx, __shfl_xor_sync(0xffffffffu, mx, 1));
            mx = fmaxf(mx, __shfl_xor_sync(0xffffffffu, mx, 2));
            float mnew  = fmaxf(mrow[half], mx);
            float alpha = __expf(mrow[half] - mnew);
            mrow[half]  = mnew;

            float rs = 0.f;
            #pragma unroll
            for (int nt = 0; nt < 8; nt++) {
                #pragma unroll
                for (int d = 0; d < 2; d++) {
                    float p = __expf(c[nt][2 * half + d] - mnew);
                    c[nt][2 * half + d] = p;
                    rs += p;
                }
            }
            rs += __shfl_xor_sync(0xffffffffu, rs, 1);
            rs += __shfl_xor_sync(0xffffffffu, rs, 2);
            lrow[half] = lrow[half] * alpha + rs;

            #pragma unroll
            for (int nt = 0; nt < 8; nt++) {
                O[nt][2 * half]     *= alpha;
                O[nt][2 * half + 1] *= alpha;
            }
            // store P (tf32) into warp-private rows of Ps
            #pragma unroll
            for (int nt = 0; nt < 8; nt++) {
                uint2 pp;
                pp.x = f2tf(c[nt][2 * half]);
                pp.y = f2tf(c[nt][2 * half + 1]);
                *(uint2*)(Ps + (rb + g + 8 * half) * SK + nt * 8 + 2 * l4) = pp;
            }
        }
        __syncwarp();

        // ---- PV GEMM: O += P(16x64) @ V(64x64) ----
        #pragma unroll
        for (int k8 = 0; k8 < 8; k8++) {
            const uint32_t* pr = Ps + (rb + g) * SK + k8 * 8 + l4;
            uint32_t a0 = pr[0];
            uint32_t a1 = pr[8 * SK];
            uint32_t a2 = pr[4];
            uint32_t a3 = pr[8 * SK + 4];
            #pragma unroll
            for (int nt = 0; nt < 8; nt++) {
                const uint32_t* vr = Vs + (k8 * 8 + l4) * SK + nt * 8 + g;
                mma8(O[nt], a0, a1, a2, a3, vr[0], vr[4 * SK]);
            }
        }
    }

    // ---- epilogue: normalize and store ----
    float* Og = OUT + (size_t)b * S * HIDDEN + h * DH;
    #pragma unroll
    for (int half = 0; half < 2; half++) {
        float inv = 1.f / lrow[half];
        int row = q0 + rb + g + 8 * half;
        #pragma unroll
        for (int nt = 0; nt < 8; nt++) {
            float2 o;
            o.x = O[nt][2 * half]     * inv;
            o.y = O[nt][2 * half + 1] * inv;
            *(float2*)(Og + (size_t)row * HIDDEN + nt * 8 + 2 * l4) = o;
        }
    }
}

extern "C" void kernel_launch(void* const* d_in, const int* in_sizes, int n_in,
                              void* d_out, int out_size)
{
    const float* x   = (const float*)d_in[0];
    const float* y   = (const float*)d_in[1];
    const float* z   = (const float*)d_in[2];
    const float* pad = (const float*)d_in[3];
    float* out = (float*)d_out;

    const int S = SEQ;
    const int B = in_sizes[3] / S;

    const size_t smem_bytes = (size_t)4 * 64 * SK * sizeof(uint32_t) + 64 * sizeof(float);
    cudaFuncSetAttribute(fa_tf32_kernel,
                         cudaFuncAttributeMaxDynamicSharedMemorySize,
                         (int)smem_bytes);

    dim3 grid(S / 64, HEADS, B);
    fa_tf32_kernel<<<grid, 128, smem_bytes>>>(x, y, z, pad, out, S);
}